// round 5
// baseline (speedup 1.0000x reference)
#include <cuda_runtime.h>
#include <cuda_fp16.h>
#include <cstdint>

#define D 128
#define MAXN 100000
#define MAXE 1600000
#define SCAN_NB ((MAXN + 255) / 256)   // 391

// ---- scratch (__device__ globals per allocation rules) ----
__device__ __half g_mh[(size_t)MAXN * D];  // m = h @ W_nb^T in fp16 (25.6 MB)
__device__ int   g_cnt[MAXN];
__device__ int   g_rowstart[MAXN];
__device__ int   g_cursor[MAXN];
__device__ int   g_scol[MAXE];
__device__ float g_sval[MAXE];
__device__ int   g_blocksums[SCAN_NB + 1];
__device__ int   g_is64;

// ---- f32x2 packed-FMA helpers (Blackwell FFMA2) ----
__device__ __forceinline__ unsigned long long pack2(float x) {
    unsigned long long r;
    asm("mov.b64 %0, {%1, %1};" : "=l"(r) : "f"(x));
    return r;
}
__device__ __forceinline__ void ffma2(unsigned long long& c,
                                      unsigned long long a,
                                      unsigned long long b) {
    asm("fma.rn.f32x2 %0, %1, %2, %0;" : "+l"(c) : "l"(a), "l"(b));
}
__device__ __forceinline__ float2 unpack2(unsigned long long v) {
    float lo, hi;
    asm("mov.b64 {%0, %1}, %2;" : "=f"(lo), "=f"(hi) : "l"(v));
    return make_float2(lo, hi);
}

// ---------------------------------------------------------------------------
// CSR build kernels (unchanged)
// ---------------------------------------------------------------------------
__global__ void zero_detect_kernel(const int* __restrict__ er, int N) {
    int i = blockIdx.x * blockDim.x + threadIdx.x;
    if (i < N) { g_cnt[i] = 0; g_cursor[i] = 0; }
    if (i == 0) {
        int f = 1;
#pragma unroll
        for (int k = 1; k < 64; k += 2) f &= (er[k] == 0);
        g_is64 = f;
    }
}

__global__ void hist_kernel(const void* __restrict__ er, int E) {
    int e = blockIdx.x * blockDim.x + threadIdx.x;
    if (e >= E) return;
    int row = g_is64 ? (int)((const long long*)er)[e] : ((const int*)er)[e];
    atomicAdd(&g_cnt[row], 1);
}

__global__ void scan_sums_kernel(int N) {
    __shared__ int sh[256];
    int i = blockIdx.x * 256 + threadIdx.x;
    int v = (i < N) ? g_cnt[i] : 0;
    sh[threadIdx.x] = v;
    __syncthreads();
#pragma unroll
    for (int off = 128; off > 0; off >>= 1) {
        if (threadIdx.x < off) sh[threadIdx.x] += sh[threadIdx.x + off];
        __syncthreads();
    }
    if (threadIdx.x == 0) g_blocksums[blockIdx.x] = sh[0];
}

__global__ void scan_top_kernel(int nb) {
    __shared__ int sh[512];
    int t = threadIdx.x;
    int v = (t < nb) ? g_blocksums[t] : 0;
    sh[t] = v;
    __syncthreads();
#pragma unroll
    for (int off = 1; off < 512; off <<= 1) {
        int tmp = (t >= off) ? sh[t - off] : 0;
        __syncthreads();
        sh[t] += tmp;
        __syncthreads();
    }
    if (t < nb) g_blocksums[t] = sh[t] - v;   // exclusive
}

__global__ void scan_local_kernel(int N) {
    __shared__ int sh[256];
    int i = blockIdx.x * 256 + threadIdx.x;
    int t = threadIdx.x;
    int v = (i < N) ? g_cnt[i] : 0;
    sh[t] = v;
    __syncthreads();
#pragma unroll
    for (int off = 1; off < 256; off <<= 1) {
        int tmp = (t >= off) ? sh[t - off] : 0;
        __syncthreads();
        sh[t] += tmp;
        __syncthreads();
    }
    if (i < N) g_rowstart[i] = sh[t] - v + g_blocksums[blockIdx.x];
}

__global__ void bucket_kernel(const float* __restrict__ ev,
                              const void* __restrict__ er,
                              const void* __restrict__ ec,
                              int E) {
    int e = blockIdx.x * blockDim.x + threadIdx.x;
    if (e >= E) return;
    int row, col;
    if (g_is64) {
        row = (int)((const long long*)er)[e];
        col = (int)((const long long*)ec)[e];
    } else {
        row = ((const int*)er)[e];
        col = ((const int*)ec)[e];
    }
    int pos = g_rowstart[row] + atomicAdd(&g_cursor[row], 1);
    g_scol[pos] = col;
    g_sval[pos] = ev[e];
}

// ---------------------------------------------------------------------------
// Fused dual GEMM: 128x128 CTA, 256 threads, 8 rows x 8 cols per thread per
// matrix (FMA-bound: 6 LDS.128 per 64 FFMA2 per warp-kstep).
// A tile double-buffered; W tiles single-buffered (re-stored per stage from
// prefetched regs — costs 2 barriers vs 4096-cyc compute body).
//   out[r][n] = h@W_self^T + b_self + b_nb ;  g_mh[r][n] = fp16(h@W_nb^T)
// ---------------------------------------------------------------------------
#define GEMM_LOAD(K0)                                                          \
    do {                                                                       \
        _Pragma("unroll")                                                      \
        for (int i = 0; i < 2; i++) {                                          \
            av[i] = make_float4(0.f, 0.f, 0.f, 0.f);                           \
            if (r0 + rr[i] < N)                                                \
                av[i] = *(const float4*)&h[(size_t)(r0 + rr[i]) * D + (K0) + qq[i] * 4]; \
            w1v[i] = *(const float4*)&Wsf[(size_t)rr[i] * D + (K0) + qq[i] * 4]; \
            w2v[i] = *(const float4*)&Wnb[(size_t)rr[i] * D + (K0) + qq[i] * 4]; \
        }                                                                      \
    } while (0)

#define GEMM_STS_A(S)                                                          \
    do {                                                                       \
        _Pragma("unroll")                                                      \
        for (int i = 0; i < 2; i++) {                                          \
            As[S][qq[i] * 4 + 0][rr[i]] = av[i].x;                             \
            As[S][qq[i] * 4 + 1][rr[i]] = av[i].y;                             \
            As[S][qq[i] * 4 + 2][rr[i]] = av[i].z;                             \
            As[S][qq[i] * 4 + 3][rr[i]] = av[i].w;                             \
        }                                                                      \
    } while (0)

#define GEMM_STS_W()                                                           \
    do {                                                                       \
        _Pragma("unroll")                                                      \
        for (int i = 0; i < 2; i++) {                                          \
            W1s[qq[i] * 4 + 0][rr[i]] = w1v[i].x;                              \
            W1s[qq[i] * 4 + 1][rr[i]] = w1v[i].y;                              \
            W1s[qq[i] * 4 + 2][rr[i]] = w1v[i].z;                              \
            W1s[qq[i] * 4 + 3][rr[i]] = w1v[i].w;                              \
            W2s[qq[i] * 4 + 0][rr[i]] = w2v[i].x;                              \
            W2s[qq[i] * 4 + 1][rr[i]] = w2v[i].y;                              \
            W2s[qq[i] * 4 + 2][rr[i]] = w2v[i].z;                              \
            W2s[qq[i] * 4 + 3][rr[i]] = w2v[i].w;                              \
        }                                                                      \
    } while (0)

__global__ __launch_bounds__(256, 1)
void gemm_dual_kernel(const float* __restrict__ h,
                      const float* __restrict__ Wsf,
                      const float* __restrict__ bsf,
                      const float* __restrict__ Wnb,
                      const float* __restrict__ bnb,
                      float* __restrict__ out,
                      int N) {
    __shared__ float As[2][16][132];   // A^T: As[s][k][r], 128 rows + pad
    __shared__ float W1s[16][132];     // W_self^T: W1s[k][n]
    __shared__ float W2s[16][132];     // W_nb^T

    const int tid = threadIdx.x;
    const int cg = tid & 15;           // cols cg*8 .. cg*8+7
    const int rg = tid >> 4;           // rows rg*8 .. rg*8+7
    const int r0 = blockIdx.x * 128;

    unsigned long long c1[8][4], c2[8][4];  // 8 rows x 4 col-pairs per matrix
#pragma unroll
    for (int i = 0; i < 8; i++)
#pragma unroll
        for (int j = 0; j < 4; j++) { c1[i][j] = 0ull; c2[i][j] = 0ull; }

    int rr[2], qq[2];
#pragma unroll
    for (int i = 0; i < 2; i++) {
        int idx = tid + i * 256;       // 0..511
        rr[i] = idx >> 2;              // row 0..127
        qq[i] = idx & 3;               // k-quad
    }

    float4 av[2], w1v[2], w2v[2];

    // prologue
    GEMM_LOAD(0);
    GEMM_STS_A(0);
    GEMM_STS_W();
    __syncthreads();

#pragma unroll
    for (int it = 0; it < 8; it++) {
        const int cur = it & 1;
        if (it < 7) GEMM_LOAD((it + 1) * 16);   // prefetch next stage

#pragma unroll
        for (int kk = 0; kk < 16; kk++) {
            float4 a0 = *(const float4*)&As[cur][kk][rg * 8];
            float4 a1 = *(const float4*)&As[cur][kk][rg * 8 + 4];
            ulonglong2 w1a = *(const ulonglong2*)&W1s[kk][cg * 8];
            ulonglong2 w1b = *(const ulonglong2*)&W1s[kk][cg * 8 + 4];
            ulonglong2 w2a = *(const ulonglong2*)&W2s[kk][cg * 8];
            ulonglong2 w2b = *(const ulonglong2*)&W2s[kk][cg * 8 + 4];
            float a[8] = {a0.x, a0.y, a0.z, a0.w, a1.x, a1.y, a1.z, a1.w};
#pragma unroll
            for (int i = 0; i < 8; i++) {
                unsigned long long ap = pack2(a[i]);
                ffma2(c1[i][0], ap, w1a.x);
                ffma2(c1[i][1], ap, w1a.y);
                ffma2(c1[i][2], ap, w1b.x);
                ffma2(c1[i][3], ap, w1b.y);
                ffma2(c2[i][0], ap, w2a.x);
                ffma2(c2[i][1], ap, w2a.y);
                ffma2(c2[i][2], ap, w2b.x);
                ffma2(c2[i][3], ap, w2b.y);
            }
        }

        if (it < 7) {
            __syncthreads();          // everyone done reading As[cur^1]/W of it
            GEMM_STS_A(cur ^ 1);
            GEMM_STS_W();
            __syncthreads();
        }
    }

    // ---- epilogue
    float4 bs0 = *(const float4*)&bsf[cg * 8];
    float4 bs1 = *(const float4*)&bsf[cg * 8 + 4];
    float4 bn0 = *(const float4*)&bnb[cg * 8];
    float4 bn1 = *(const float4*)&bnb[cg * 8 + 4];
    float bb[8] = {bs0.x + bn0.x, bs0.y + bn0.y, bs0.z + bn0.z, bs0.w + bn0.w,
                   bs1.x + bn1.x, bs1.y + bn1.y, bs1.z + bn1.z, bs1.w + bn1.w};

#pragma unroll
    for (int i = 0; i < 8; i++) {
        int r = r0 + rg * 8 + i;
        if (r < N) {
            float2 p0 = unpack2(c1[i][0]);
            float2 p1 = unpack2(c1[i][1]);
            float2 p2 = unpack2(c1[i][2]);
            float2 p3 = unpack2(c1[i][3]);
            *(float4*)&out[(size_t)r * D + cg * 8] =
                make_float4(p0.x + bb[0], p0.y + bb[1], p1.x + bb[2], p1.y + bb[3]);
            *(float4*)&out[(size_t)r * D + cg * 8 + 4] =
                make_float4(p2.x + bb[4], p2.y + bb[5], p3.x + bb[6], p3.y + bb[7]);
            float2 q0 = unpack2(c2[i][0]);
            float2 q1 = unpack2(c2[i][1]);
            float2 q2 = unpack2(c2[i][2]);
            float2 q3 = unpack2(c2[i][3]);
            union { __half2 h2[4]; uint4 u; } uu;
            uu.h2[0] = __floats2half2_rn(q0.x, q0.y);
            uu.h2[1] = __floats2half2_rn(q1.x, q1.y);
            uu.h2[2] = __floats2half2_rn(q2.x, q2.y);
            uu.h2[3] = __floats2half2_rn(q3.x, q3.y);
            *(uint4*)&g_mh[(size_t)r * D + cg * 8] = uu.u;
        }
    }
}

// ---------------------------------------------------------------------------
// Aggregation over fp16 m. One warp per row, fp32 register accumulation.
// ---------------------------------------------------------------------------
__global__ __launch_bounds__(256)
void aggregate_kernel(float* __restrict__ out, int N) {
    const int warp = threadIdx.x >> 5;
    const int lane = threadIdx.x & 31;
    const int r = blockIdx.x * 8 + warp;
    if (r >= N) return;

    const int start = g_rowstart[r];
    const int cnt = g_cnt[r];
    if (cnt == 0) return;

    const uint2* __restrict__ m2 = (const uint2*)g_mh;
    float4 acc = make_float4(0.f, 0.f, 0.f, 0.f);

    int i = 0;
    for (; i + 2 <= cnt; i += 2) {
        int c0 = g_scol[start + i];
        int c1 = g_scol[start + i + 1];
        float v0 = g_sval[start + i];
        float v1 = g_sval[start + i + 1];
        uint2 r0 = m2[(size_t)c0 * 32 + lane];
        uint2 r1 = m2[(size_t)c1 * 32 + lane];
        float2 f00 = __half22float2(*(__half2*)&r0.x);
        float2 f01 = __half22float2(*(__half2*)&r0.y);
        float2 f10 = __half22float2(*(__half2*)&r1.x);
        float2 f11 = __half22float2(*(__half2*)&r1.y);
        acc.x = fmaf(v0, f00.x, acc.x); acc.y = fmaf(v0, f00.y, acc.y);
        acc.z = fmaf(v0, f01.x, acc.z); acc.w = fmaf(v0, f01.y, acc.w);
        acc.x = fmaf(v1, f10.x, acc.x); acc.y = fmaf(v1, f10.y, acc.y);
        acc.z = fmaf(v1, f11.x, acc.z); acc.w = fmaf(v1, f11.y, acc.w);
    }
    if (i < cnt) {
        int c0 = g_scol[start + i];
        float v0 = g_sval[start + i];
        uint2 r0 = m2[(size_t)c0 * 32 + lane];
        float2 f00 = __half22float2(*(__half2*)&r0.x);
        float2 f01 = __half22float2(*(__half2*)&r0.y);
        acc.x = fmaf(v0, f00.x, acc.x); acc.y = fmaf(v0, f00.y, acc.y);
        acc.z = fmaf(v0, f01.x, acc.z); acc.w = fmaf(v0, f01.y, acc.w);
    }

    float4* op = (float4*)out + (size_t)r * 32 + lane;
    float4 o = *op;
    o.x += acc.x; o.y += acc.y; o.z += acc.z; o.w += acc.w;
    *op = o;
}

// ---------------------------------------------------------------------------
extern "C" void kernel_launch(void* const* d_in, const int* in_sizes, int n_in,
                              void* d_out, int out_size) {
    const float* h   = (const float*)d_in[0];
    const float* ev  = (const float*)d_in[1];
    const float* Wsf = (const float*)d_in[2];
    const float* bsf = (const float*)d_in[3];
    const float* Wnb = (const float*)d_in[4];
    const float* bnb = (const float*)d_in[5];
    const void*  er  = d_in[6];
    const void*  ec  = d_in[7];
    float* out = (float*)d_out;

    const int N = in_sizes[0] / D;
    const int E = in_sizes[1];
    const int nbN = (N + 255) / 256;
    const int nbE = (E + 255) / 256;

    gemm_dual_kernel<<<(N + 127) / 128, 256>>>(h, Wsf, bsf, Wnb, bnb, out, N);

    zero_detect_kernel<<<nbN, 256>>>((const int*)er, N);
    hist_kernel<<<nbE, 256>>>(er, E);
    scan_sums_kernel<<<nbN, 256>>>(N);
    scan_top_kernel<<<1, 512>>>(nbN);
    scan_local_kernel<<<nbN, 256>>>(N);
    bucket_kernel<<<nbE, 256>>>(ev, er, ec, E);

    aggregate_kernel<<<(N + 7) / 8, 256>>>(out, N);
}

// round 6
// speedup vs baseline: 1.3773x; 1.3773x over previous
#include <cuda_runtime.h>
#include <cuda_fp16.h>
#include <cstdint>

#define D 128
#define MAXN 100000
#define MAXE 1600000

// ---- scratch (__device__ globals per allocation rules) ----
__device__ __half g_mh[(size_t)MAXN * D];  // m = h @ W_nb^T in fp16 (25.6 MB)
__device__ int   g_cnt[MAXN];
__device__ int   g_rowstart[MAXN];
__device__ int   g_cursor[MAXN];
__device__ int   g_scol[MAXE];
__device__ float g_sval[MAXE];
__device__ int   g_total;
__device__ int   g_is64;

// ---- f32x2 packed-FMA helpers (Blackwell FFMA2) ----
__device__ __forceinline__ unsigned long long pack2(float x) {
    unsigned long long r;
    asm("mov.b64 %0, {%1, %1};" : "=l"(r) : "f"(x));
    return r;
}
__device__ __forceinline__ void ffma2(unsigned long long& c,
                                      unsigned long long a,
                                      unsigned long long b) {
    asm("fma.rn.f32x2 %0, %1, %2, %0;" : "+l"(c) : "l"(a), "l"(b));
}
__device__ __forceinline__ float2 unpack2(unsigned long long v) {
    float lo, hi;
    asm("mov.b64 {%0, %1}, %2;" : "=f"(lo), "=f"(hi) : "l"(v));
    return make_float2(lo, hi);
}

// ---------------------------------------------------------------------------
// K0: zero counters + detect int64 vs int32 indices
// ---------------------------------------------------------------------------
__global__ void zero_detect_kernel(const int* __restrict__ er, int N) {
    int i = blockIdx.x * blockDim.x + threadIdx.x;
    if (i < N) g_cnt[i] = 0;
    if (i == 0) {
        g_total = 0;
        int f = 1;
#pragma unroll
        for (int k = 1; k < 64; k += 2) f &= (er[k] == 0);
        g_is64 = f;
    }
}

__global__ void hist_kernel(const void* __restrict__ er, int E) {
    int e = blockIdx.x * blockDim.x + threadIdx.x;
    if (e >= E) return;
    int row = g_is64 ? (int)((const long long*)er)[e] : ((const int*)er)[e];
    atomicAdd(&g_cnt[row], 1);
}

// ---------------------------------------------------------------------------
// K2: assign contiguous (unsorted) CSR segments: warp-scan + 1 atomic/warp.
// ---------------------------------------------------------------------------
__global__ void rowassign_kernel(int N) {
    int i = blockIdx.x * blockDim.x + threadIdx.x;
    int lane = threadIdx.x & 31;
    int v = (i < N) ? g_cnt[i] : 0;
    int s = v;
#pragma unroll
    for (int off = 1; off < 32; off <<= 1) {
        int t = __shfl_up_sync(0xFFFFFFFFu, s, off);
        if (lane >= off) s += t;
    }
    int total = __shfl_sync(0xFFFFFFFFu, s, 31);
    int base = 0;
    if (lane == 31 && total > 0) base = atomicAdd(&g_total, total);
    base = __shfl_sync(0xFFFFFFFFu, base, 31);
    if (i < N) { g_rowstart[i] = base + s - v; g_cursor[i] = 0; }
}

__global__ void bucket_kernel(const float* __restrict__ ev,
                              const void* __restrict__ er,
                              const void* __restrict__ ec,
                              int E) {
    int e = blockIdx.x * blockDim.x + threadIdx.x;
    if (e >= E) return;
    int row, col;
    if (g_is64) {
        row = (int)((const long long*)er)[e];
        col = (int)((const long long*)ec)[e];
    } else {
        row = ((const int*)er)[e];
        col = ((const int*)ec)[e];
    }
    int pos = g_rowstart[row] + atomicAdd(&g_cursor[row], 1);
    g_scol[pos] = col;
    g_sval[pos] = ev[e];
}

// ---------------------------------------------------------------------------
// Fused dual GEMM (R4 proven config): 64x128 CTA, 256 thr, 8x4 per thread
// per matrix, double-buffered smem pipeline.
//   out[r][n] = h@W_self^T + b_self + b_nb ;  g_mh[r][n] = fp16(h@W_nb^T)
// ---------------------------------------------------------------------------
#define GEMM_LOAD(K0)                                                          \
    do {                                                                       \
        av = make_float4(0.f, 0.f, 0.f, 0.f);                                  \
        if (r0 + lr < N)                                                       \
            av = *(const float4*)&h[(size_t)(r0 + lr) * D + (K0) + lk * 4];    \
        _Pragma("unroll")                                                      \
        for (int i = 0; i < 2; i++) {                                          \
            w1v[i] = *(const float4*)&Wsf[(size_t)nn[i] * D + (K0) + kk2[i] * 4]; \
            w2v[i] = *(const float4*)&Wnb[(size_t)nn[i] * D + (K0) + kk2[i] * 4]; \
        }                                                                      \
    } while (0)

#define GEMM_STS(S)                                                            \
    do {                                                                       \
        As[S][lk * 4 + 0][lr] = av.x;                                          \
        As[S][lk * 4 + 1][lr] = av.y;                                          \
        As[S][lk * 4 + 2][lr] = av.z;                                          \
        As[S][lk * 4 + 3][lr] = av.w;                                          \
        _Pragma("unroll")                                                      \
        for (int i = 0; i < 2; i++) {                                          \
            W1s[S][kk2[i] * 4 + 0][nn[i]] = w1v[i].x;                          \
            W1s[S][kk2[i] * 4 + 1][nn[i]] = w1v[i].y;                          \
            W1s[S][kk2[i] * 4 + 2][nn[i]] = w1v[i].z;                          \
            W1s[S][kk2[i] * 4 + 3][nn[i]] = w1v[i].w;                          \
            W2s[S][kk2[i] * 4 + 0][nn[i]] = w2v[i].x;                          \
            W2s[S][kk2[i] * 4 + 1][nn[i]] = w2v[i].y;                          \
            W2s[S][kk2[i] * 4 + 2][nn[i]] = w2v[i].z;                          \
            W2s[S][kk2[i] * 4 + 3][nn[i]] = w2v[i].w;                          \
        }                                                                      \
    } while (0)

__global__ __launch_bounds__(256, 2)
void gemm_dual_kernel(const float* __restrict__ h,
                      const float* __restrict__ Wsf,
                      const float* __restrict__ bsf,
                      const float* __restrict__ Wnb,
                      const float* __restrict__ bnb,
                      float* __restrict__ out,
                      int N) {
    __shared__ float As[2][16][68];
    __shared__ float W1s[2][16][132];
    __shared__ float W2s[2][16][132];

    const int tid = threadIdx.x;
    const int cg = tid & 31;
    const int rg = tid >> 5;
    const int r0 = blockIdx.x * 64;

    unsigned long long c1[8][2], c2[8][2];
#pragma unroll
    for (int i = 0; i < 8; i++)
#pragma unroll
        for (int j = 0; j < 2; j++) { c1[i][j] = 0ull; c2[i][j] = 0ull; }

    const int lr = tid >> 2;
    const int lk = tid & 3;
    int nn[2], kk2[2];
#pragma unroll
    for (int i = 0; i < 2; i++) {
        int idx = tid + i * 256;
        nn[i] = idx >> 2;
        kk2[i] = idx & 3;
    }

    float4 av, w1v[2], w2v[2];

    GEMM_LOAD(0);
    GEMM_STS(0);
    __syncthreads();

#pragma unroll
    for (int it = 0; it < 8; it++) {
        const int cur = it & 1;
        if (it < 7) GEMM_LOAD((it + 1) * 16);

#pragma unroll
        for (int kk = 0; kk < 16; kk++) {
            float4 a0 = *(const float4*)&As[cur][kk][rg * 8];
            float4 a1 = *(const float4*)&As[cur][kk][rg * 8 + 4];
            ulonglong2 w1 = *(const ulonglong2*)&W1s[cur][kk][cg * 4];
            ulonglong2 w2 = *(const ulonglong2*)&W2s[cur][kk][cg * 4];
            float a[8] = {a0.x, a0.y, a0.z, a0.w, a1.x, a1.y, a1.z, a1.w};
#pragma unroll
            for (int i = 0; i < 8; i++) {
                unsigned long long ap = pack2(a[i]);
                ffma2(c1[i][0], ap, w1.x);
                ffma2(c1[i][1], ap, w1.y);
                ffma2(c2[i][0], ap, w2.x);
                ffma2(c2[i][1], ap, w2.y);
            }
        }

        if (it < 7) {
            __syncthreads();
            GEMM_STS(cur ^ 1);
            __syncthreads();
        }
    }

    float4 bsv = *(const float4*)&bsf[cg * 4];
    float4 bnv = *(const float4*)&bnb[cg * 4];
    float bb[4] = {bsv.x + bnv.x, bsv.y + bnv.y, bsv.z + bnv.z, bsv.w + bnv.w};

#pragma unroll
    for (int i = 0; i < 8; i++) {
        int r = r0 + rg * 8 + i;
        if (r < N) {
            float2 p0 = unpack2(c1[i][0]);
            float2 p1 = unpack2(c1[i][1]);
            *(float4*)&out[(size_t)r * D + cg * 4] =
                make_float4(p0.x + bb[0], p0.y + bb[1], p1.x + bb[2], p1.y + bb[3]);
            float2 q0 = unpack2(c2[i][0]);
            float2 q1 = unpack2(c2[i][1]);
            union { __half2 h2[2]; uint2 u; } uu;
            uu.h2[0] = __floats2half2_rn(q0.x, q0.y);
            uu.h2[1] = __floats2half2_rn(q1.x, q1.y);
            *(uint2*)&g_mh[(size_t)r * D + cg * 4] = uu.u;
        }
    }
}

// ---------------------------------------------------------------------------
// Aggregation over fp16 m. One warp per row, fp32 accumulation, 4-way MLP.
// ---------------------------------------------------------------------------
__global__ __launch_bounds__(256)
void aggregate_kernel(float* __restrict__ out, int N) {
    const int warp = threadIdx.x >> 5;
    const int lane = threadIdx.x & 31;
    const int r = blockIdx.x * 8 + warp;
    if (r >= N) return;

    const int start = g_rowstart[r];
    const int cnt = g_cnt[r];
    if (cnt == 0) return;

    const uint2* __restrict__ m2 = (const uint2*)g_mh;
    float4 acc = make_float4(0.f, 0.f, 0.f, 0.f);

    int i = 0;
    for (; i + 4 <= cnt; i += 4) {
        int c0 = g_scol[start + i];
        int c1 = g_scol[start + i + 1];
        int c2 = g_scol[start + i + 2];
        int c3 = g_scol[start + i + 3];
        float v0 = g_sval[start + i];
        float v1 = g_sval[start + i + 1];
        float v2 = g_sval[start + i + 2];
        float v3 = g_sval[start + i + 3];
        uint2 r0 = m2[(size_t)c0 * 32 + lane];
        uint2 r1 = m2[(size_t)c1 * 32 + lane];
        uint2 r2 = m2[(size_t)c2 * 32 + lane];
        uint2 r3 = m2[(size_t)c3 * 32 + lane];
        float2 f0a = __half22float2(*(__half2*)&r0.x);
        float2 f0b = __half22float2(*(__half2*)&r0.y);
        float2 f1a = __half22float2(*(__half2*)&r1.x);
        float2 f1b = __half22float2(*(__half2*)&r1.y);
        float2 f2a = __half22float2(*(__half2*)&r2.x);
        float2 f2b = __half22float2(*(__half2*)&r2.y);
        float2 f3a = __half22float2(*(__half2*)&r3.x);
        float2 f3b = __half22float2(*(__half2*)&r3.y);
        acc.x = fmaf(v0, f0a.x, acc.x); acc.y = fmaf(v0, f0a.y, acc.y);
        acc.z = fmaf(v0, f0b.x, acc.z); acc.w = fmaf(v0, f0b.y, acc.w);
        acc.x = fmaf(v1, f1a.x, acc.x); acc.y = fmaf(v1, f1a.y, acc.y);
        acc.z = fmaf(v1, f1b.x, acc.z); acc.w = fmaf(v1, f1b.y, acc.w);
        acc.x = fmaf(v2, f2a.x, acc.x); acc.y = fmaf(v2, f2a.y, acc.y);
        acc.z = fmaf(v2, f2b.x, acc.z); acc.w = fmaf(v2, f2b.y, acc.w);
        acc.x = fmaf(v3, f3a.x, acc.x); acc.y = fmaf(v3, f3a.y, acc.y);
        acc.z = fmaf(v3, f3b.x, acc.z); acc.w = fmaf(v3, f3b.y, acc.w);
    }
    for (; i < cnt; i++) {
        int c0 = g_scol[start + i];
        float v0 = g_sval[start + i];
        uint2 r0 = m2[(size_t)c0 * 32 + lane];
        float2 f0a = __half22float2(*(__half2*)&r0.x);
        float2 f0b = __half22float2(*(__half2*)&r0.y);
        acc.x = fmaf(v0, f0a.x, acc.x); acc.y = fmaf(v0, f0a.y, acc.y);
        acc.z = fmaf(v0, f0b.x, acc.z); acc.w = fmaf(v0, f0b.y, acc.w);
    }

    float4* op = (float4*)out + (size_t)r * 32 + lane;
    float4 o = *op;
    o.x += acc.x; o.y += acc.y; o.z += acc.z; o.w += acc.w;
    *op = o;
}

// ---------------------------------------------------------------------------
extern "C" void kernel_launch(void* const* d_in, const int* in_sizes, int n_in,
                              void* d_out, int out_size) {
    const float* h   = (const float*)d_in[0];
    const float* ev  = (const float*)d_in[1];
    const float* Wsf = (const float*)d_in[2];
    const float* bsf = (const float*)d_in[3];
    const float* Wnb = (const float*)d_in[4];
    const float* bnb = (const float*)d_in[5];
    const void*  er  = d_in[6];
    const void*  ec  = d_in[7];
    float* out = (float*)d_out;

    const int N = in_sizes[0] / D;
    const int E = in_sizes[1];
    const int nbN = (N + 255) / 256;
    const int nbE = (E + 255) / 256;

    gemm_dual_kernel<<<(N + 63) / 64, 256>>>(h, Wsf, bsf, Wnb, bnb, out, N);

    zero_detect_kernel<<<nbN, 256>>>((const int*)er, N);
    hist_kernel<<<nbE, 256>>>(er, E);
    rowassign_kernel<<<nbN, 256>>>(N);
    bucket_kernel<<<nbE, 256>>>(ev, er, ec, E);

    aggregate_kernel<<<(N + 7) / 8, 256>>>(out, N);
}

// round 8
// speedup vs baseline: 1.3938x; 1.0120x over previous
#include <cuda_runtime.h>
#include <cuda_fp16.h>
#include <cuda_bf16.h>
#include <cstdint>

#define D 128
#define MAXN 100000
#define MAXE 1600000
#define BSTR 136   // padded row stride (bf16 elems): 272B -> conflict-free ldmatrix

// ---- scratch (__device__ globals per allocation rules) ----
__device__ __half g_mh[(size_t)MAXN * D];              // m = h @ W_nb^T (fp16)
__device__ __align__(16) __nv_bfloat16 g_wb[2 * 256 * BSTR];  // B' images: [sel][n][k]
__device__ float g_bias[D];                            // b_self + b_nb
__device__ int   g_cnt[MAXN];
__device__ int   g_rowstart[MAXN];
__device__ int   g_cursor[MAXN];
__device__ int   g_scol[MAXE];
__device__ float g_sval[MAXE];
__device__ int   g_total;
__device__ int   g_is64;

// smem layout for the MMA GEMM
#define SME_B    0                          // [2][256][BSTR] bf16 = 139264 B
#define SME_A    (2 * 256 * BSTR * 2)       // [2][128][BSTR] bf16 = 69632 B
#define SME_BIAS (SME_A + 2 * 128 * BSTR * 2)
#define SME_TOTAL (SME_BIAS + 512)          // 209408 B

__device__ __forceinline__ uint32_t smem_u32(const void* p) {
    uint32_t a;
    asm("{ .reg .u64 t; cvta.to.shared.u64 t, %1; cvt.u32.u64 %0, t; }"
        : "=r"(a) : "l"(p));
    return a;
}

#define LDSM_X4(r0, r1, r2, r3, addr)                                          \
    asm volatile("ldmatrix.sync.aligned.m8n8.x4.shared.b16 {%0,%1,%2,%3}, [%4];" \
                 : "=r"(r0), "=r"(r1), "=r"(r2), "=r"(r3) : "r"(addr))

__device__ __forceinline__ void mma16816(float* c, const uint32_t* a,
                                         uint32_t b0, uint32_t b1) {
    asm volatile(
        "mma.sync.aligned.m16n8k16.row.col.f32.bf16.bf16.f32 "
        "{%0,%1,%2,%3}, {%4,%5,%6,%7}, {%8,%9}, {%0,%1,%2,%3};"
        : "+f"(c[0]), "+f"(c[1]), "+f"(c[2]), "+f"(c[3])
        : "r"(a[0]), "r"(a[1]), "r"(a[2]), "r"(a[3]), "r"(b0), "r"(b1));
}

// ---------------------------------------------------------------------------
// W precompute: B' = [W_self ; W_nb] (256 output rows), split bf16 hi/lo,
// stored in the padded ldmatrix-ready layout. Plus summed bias.
// ---------------------------------------------------------------------------
__global__ void wconvert_kernel(const float* __restrict__ Wsf,
                                const float* __restrict__ Wnb,
                                const float* __restrict__ bsf,
                                const float* __restrict__ bnb) {
    int idx = blockIdx.x * blockDim.x + threadIdx.x;   // 0..32767
    if (idx < 256 * 128) {
        int n = idx >> 7;
        int k = idx & 127;
        float x = (n < 128) ? Wsf[n * D + k] : Wnb[(n - 128) * D + k];
        __nv_bfloat16 hi = __float2bfloat16_rn(x);
        __nv_bfloat16 lo = __float2bfloat16_rn(x - __bfloat162float(hi));
        g_wb[(size_t)n * BSTR + k] = hi;
        g_wb[(size_t)(256 + n) * BSTR + k] = lo;
    }
    if (blockIdx.x == 0 && threadIdx.x < D)
        g_bias[threadIdx.x] = bsf[threadIdx.x] + bnb[threadIdx.x];
}

// ---------------------------------------------------------------------------
// Tensor-core dual GEMM via mma.sync bf16 (split precision, virtual K=384):
//   C[128x256] = A'[128x384] x B'[384x256]
//   kb 0-7:  A_hi x B_hi ; kb 8-15: A_lo x B_hi ; kb 16-23: A_hi x B_lo
//   cols 0-127 -> out (+bias) ; cols 128-255 -> g_mh (fp16)
// 512 threads, 16 warps, warp tile 32 rows x 64 cols.
// ---------------------------------------------------------------------------
__global__ __launch_bounds__(512, 1)
void gemm_mma_kernel(const float* __restrict__ h, float* __restrict__ out, int N) {
    extern __shared__ char smem[];
    const uint32_t sb = smem_u32(smem);
    const int tid = threadIdx.x;
    const int wid = tid >> 5;
    const int lane = tid & 31;
    const int r0 = blockIdx.x * 128;
    const int wrow = (wid >> 2) * 32;      // warp row base (0,32,64,96)
    const int wcol = (wid & 3) * 64;       // warp col base (0,64,128,192)

    // ---- copy B' images (139264 B)
    {
        const uint4* src = (const uint4*)g_wb;
        uint4* dst = (uint4*)(smem + SME_B);
        for (int i = tid; i < 2 * 256 * BSTR * 2 / 16; i += 512) dst[i] = src[i];
    }
    if (tid < D) ((float*)(smem + SME_BIAS))[tid] = g_bias[tid];

    // ---- load h tile, split bf16 hi/lo into A' smem
    __nv_bfloat16* As = (__nv_bfloat16*)(smem + SME_A);
    for (int c = tid; c < 2048; c += 512) {   // 128 rows x 16 chunks of 8
        int row = c >> 4, cc = c & 15;
        int r = r0 + row;
        float xs[8] = {0.f, 0.f, 0.f, 0.f, 0.f, 0.f, 0.f, 0.f};
        if (r < N) {
            float4 x0 = *(const float4*)&h[(size_t)r * D + cc * 8];
            float4 x1 = *(const float4*)&h[(size_t)r * D + cc * 8 + 4];
            xs[0] = x0.x; xs[1] = x0.y; xs[2] = x0.z; xs[3] = x0.w;
            xs[4] = x1.x; xs[5] = x1.y; xs[6] = x1.z; xs[7] = x1.w;
        }
        __nv_bfloat16 hi[8], lo[8];
#pragma unroll
        for (int j = 0; j < 8; j++) {
            hi[j] = __float2bfloat16_rn(xs[j]);
            lo[j] = __float2bfloat16_rn(xs[j] - __bfloat162float(hi[j]));
        }
        *(uint4*)&As[(size_t)row * BSTR + cc * 8] = *(uint4*)hi;
        *(uint4*)&As[(size_t)(128 + row) * BSTR + cc * 8] = *(uint4*)lo;
    }
    __syncthreads();

    float acc[2][8][4];
#pragma unroll
    for (int mi = 0; mi < 2; mi++)
#pragma unroll
        for (int ni = 0; ni < 8; ni++)
#pragma unroll
            for (int j = 0; j < 4; j++) acc[mi][ni][j] = 0.f;

    const int lrow = ((lane >> 3) & 1) * 8 + (lane & 7);  // ldmatrix row-in-tile
    const int lcol = (lane >> 4) * 8;                     // ldmatrix col offset

#pragma unroll
    for (int kb = 0; kb < 24; kb++) {
        const int asel = ((kb >> 3) == 1) ? 1 : 0;        // lo for kb 8-15
        const int bsel = ((kb >> 3) == 2) ? 1 : 0;        // lo for kb 16-23
        const int k0 = (kb & 7) * 16;

        // A fragments: 2 m-tiles of 16x16
        uint32_t a[2][4];
#pragma unroll
        for (int mi = 0; mi < 2; mi++) {
            int row = asel * 128 + wrow + mi * 16 + lrow;
            uint32_t ad = sb + SME_A + (uint32_t)(row * BSTR + k0 + lcol) * 2;
            LDSM_X4(a[mi][0], a[mi][1], a[mi][2], a[mi][3], ad);
        }
        // B fragments: 4 ldmatrix.x4, each covers 2 n-tiles x full k16
        uint32_t b[4][4];
#pragma unroll
        for (int np = 0; np < 4; np++) {
            int nrow = bsel * 256 + wcol + np * 16 + lrow;
            uint32_t bd = sb + SME_B + (uint32_t)(nrow * BSTR + k0 + lcol) * 2;
            LDSM_X4(b[np][0], b[np][1], b[np][2], b[np][3], bd);
        }
#pragma unroll
        for (int mi = 0; mi < 2; mi++)
#pragma unroll
            for (int np = 0; np < 4; np++) {
                mma16816(acc[mi][np * 2 + 0], a[mi], b[np][0], b[np][2]);
                mma16816(acc[mi][np * 2 + 1], a[mi], b[np][1], b[np][3]);
            }
    }

    // ---- epilogue. thread holds c[row = wrow+mi*16+8*i+lane/4][col = wcol+ni*8+2*(lane%4)+j]
    const float* sbias = (const float*)(smem + SME_BIAS);
    const int rbase = r0 + wrow + (lane >> 2);
    const int cbase = wcol + 2 * (lane & 3);

    if (wcol < 128) {
        // -> out with bias
#pragma unroll
        for (int mi = 0; mi < 2; mi++)
#pragma unroll
            for (int i = 0; i < 2; i++) {
                int r = rbase + mi * 16 + 8 * i;
                if (r < N) {
#pragma unroll
                    for (int ni = 0; ni < 8; ni++) {
                        int c = cbase + ni * 8;
                        float2 v = make_float2(acc[mi][ni][2 * i] + sbias[c],
                                               acc[mi][ni][2 * i + 1] + sbias[c + 1]);
                        *(float2*)&out[(size_t)r * D + c] = v;
                    }
                }
            }
    } else {
        // -> g_mh fp16
        const int cm = cbase - 128;
#pragma unroll
        for (int mi = 0; mi < 2; mi++)
#pragma unroll
            for (int i = 0; i < 2; i++) {
                int r = rbase + mi * 16 + 8 * i;
                if (r < N) {
#pragma unroll
                    for (int ni = 0; ni < 8; ni++) {
                        int c = cm + ni * 8;
                        __half2 v = __floats2half2_rn(acc[mi][ni][2 * i],
                                                      acc[mi][ni][2 * i + 1]);
                        *(__half2*)&g_mh[(size_t)r * D + c] = v;
                    }
                }
            }
    }
}

// ---------------------------------------------------------------------------
// CSR build (unchanged)
// ---------------------------------------------------------------------------
__global__ void zero_detect_kernel(const int* __restrict__ er, int N) {
    int i = blockIdx.x * blockDim.x + threadIdx.x;
    if (i < N) g_cnt[i] = 0;
    if (i == 0) {
        g_total = 0;
        int f = 1;
#pragma unroll
        for (int k = 1; k < 64; k += 2) f &= (er[k] == 0);
        g_is64 = f;
    }
}

__global__ void hist_kernel(const void* __restrict__ er, int E) {
    int e = blockIdx.x * blockDim.x + threadIdx.x;
    if (e >= E) return;
    int row = g_is64 ? (int)((const long long*)er)[e] : ((const int*)er)[e];
    atomicAdd(&g_cnt[row], 1);
}

__global__ void rowassign_kernel(int N) {
    int i = blockIdx.x * blockDim.x + threadIdx.x;
    int lane = threadIdx.x & 31;
    int v = (i < N) ? g_cnt[i] : 0;
    int s = v;
#pragma unroll
    for (int off = 1; off < 32; off <<= 1) {
        int t = __shfl_up_sync(0xFFFFFFFFu, s, off);
        if (lane >= off) s += t;
    }
    int total = __shfl_sync(0xFFFFFFFFu, s, 31);
    int base = 0;
    if (lane == 31 && total > 0) base = atomicAdd(&g_total, total);
    base = __shfl_sync(0xFFFFFFFFu, base, 31);
    if (i < N) { g_rowstart[i] = base + s - v; g_cursor[i] = 0; }
}

__global__ void bucket_kernel(const float* __restrict__ ev,
                              const void* __restrict__ er,
                              const void* __restrict__ ec,
                              int E) {
    int e = blockIdx.x * blockDim.x + threadIdx.x;
    if (e >= E) return;
    int row, col;
    if (g_is64) {
        row = (int)((const long long*)er)[e];
        col = (int)((const long long*)ec)[e];
    } else {
        row = ((const int*)er)[e];
        col = ((const int*)ec)[e];
    }
    int pos = g_rowstart[row] + atomicAdd(&g_cursor[row], 1);
    g_scol[pos] = col;
    g_sval[pos] = ev[e];
}

// ---------------------------------------------------------------------------
// Aggregation over fp16 m (unchanged)
// ---------------------------------------------------------------------------
__global__ __launch_bounds__(256)
void aggregate_kernel(float* __restrict__ out, int N) {
    const int warp = threadIdx.x >> 5;
    const int lane = threadIdx.x & 31;
    const int r = blockIdx.x * 8 + warp;
    if (r >= N) return;

    const int start = g_rowstart[r];
    const int cnt = g_cnt[r];
    if (cnt == 0) return;

    const uint2* __restrict__ m2 = (const uint2*)g_mh;
    float4 acc = make_float4(0.f, 0.f, 0.f, 0.f);

    int i = 0;
    for (; i + 4 <= cnt; i += 4) {
        int c0 = g_scol[start + i];
        int c1 = g_scol[start + i + 1];
        int c2 = g_scol[start + i + 2];
        int c3 = g_scol[start + i + 3];
        float v0 = g_sval[start + i];
        float v1 = g_sval[start + i + 1];
        float v2 = g_sval[start + i + 2];
        float v3 = g_sval[start + i + 3];
        uint2 r0 = m2[(size_t)c0 * 32 + lane];
        uint2 r1 = m2[(size_t)c1 * 32 + lane];
        uint2 r2 = m2[(size_t)c2 * 32 + lane];
        uint2 r3 = m2[(size_t)c3 * 32 + lane];
        float2 f0a = __half22float2(*(__half2*)&r0.x);
        float2 f0b = __half22float2(*(__half2*)&r0.y);
        float2 f1a = __half22float2(*(__half2*)&r1.x);
        float2 f1b = __half22float2(*(__half2*)&r1.y);
        float2 f2a = __half22float2(*(__half2*)&r2.x);
        float2 f2b = __half22float2(*(__half2*)&r2.y);
        float2 f3a = __half22float2(*(__half2*)&r3.x);
        float2 f3b = __half22float2(*(__half2*)&r3.y);
        acc.x = fmaf(v0, f0a.x, acc.x); acc.y = fmaf(v0, f0a.y, acc.y);
        acc.z = fmaf(v0, f0b.x, acc.z); acc.w = fmaf(v0, f0b.y, acc.w);
        acc.x = fmaf(v1, f1a.x, acc.x); acc.y = fmaf(v1, f1a.y, acc.y);
        acc.z = fmaf(v1, f1b.x, acc.z); acc.w = fmaf(v1, f1b.y, acc.w);
        acc.x = fmaf(v2, f2a.x, acc.x); acc.y = fmaf(v2, f2a.y, acc.y);
        acc.z = fmaf(v2, f2b.x, acc.z); acc.w = fmaf(v2, f2b.y, acc.w);
        acc.x = fmaf(v3, f3a.x, acc.x); acc.y = fmaf(v3, f3a.y, acc.y);
        acc.z = fmaf(v3, f3b.x, acc.z); acc.w = fmaf(v3, f3b.y, acc.w);
    }
    for (; i < cnt; i++) {
        int c0 = g_scol[start + i];
        float v0 = g_sval[start + i];
        uint2 r0 = m2[(size_t)c0 * 32 + lane];
        float2 f0a = __half22float2(*(__half2*)&r0.x);
        float2 f0b = __half22float2(*(__half2*)&r0.y);
        acc.x = fmaf(v0, f0a.x, acc.x); acc.y = fmaf(v0, f0a.y, acc.y);
        acc.z = fmaf(v0, f0b.x, acc.z); acc.w = fmaf(v0, f0b.y, acc.w);
    }

    float4* op = (float4*)out + (size_t)r * 32 + lane;
    float4 o = *op;
    o.x += acc.x; o.y += acc.y; o.z += acc.z; o.w += acc.w;
    *op = o;
}

// ---------------------------------------------------------------------------
extern "C" void kernel_launch(void* const* d_in, const int* in_sizes, int n_in,
                              void* d_out, int out_size) {
    const float* h   = (const float*)d_in[0];
    const float* ev  = (const float*)d_in[1];
    const float* Wsf = (const float*)d_in[2];
    const float* bsf = (const float*)d_in[3];
    const float* Wnb = (const float*)d_in[4];
    const float* bnb = (const float*)d_in[5];
    const void*  er  = d_in[6];
    const void*  ec  = d_in[7];
    float* out = (float*)d_out;

    const int N = in_sizes[0] / D;
    const int E = in_sizes[1];
    const int nbN = (N + 255) / 256;
    const int nbE = (E + 255) / 256;

    cudaFuncSetAttribute(gemm_mma_kernel,
                         cudaFuncAttributeMaxDynamicSharedMemorySize, SME_TOTAL);

    wconvert_kernel<<<128, 256>>>(Wsf, Wnb, bsf, bnb);
    gemm_mma_kernel<<<(N + 127) / 128, 512, SME_TOTAL>>>(h, out, N);

    zero_detect_kernel<<<nbN, 256>>>((const int*)er, N);
    hist_kernel<<<nbE, 256>>>(er, E);
    rowassign_kernel<<<nbN, 256>>>(N);
    bucket_kernel<<<nbE, 256>>>(ev, er, ec, E);

    aggregate_kernel<<<(N + 7) / 8, 256>>>(out, N);
}

// round 9
// speedup vs baseline: 1.4611x; 1.0483x over previous
#include <cuda_runtime.h>
#include <cuda_fp16.h>
#include <cuda_bf16.h>
#include <cstdint>

#define D 128
#define MAXN 100000
#define MAXE 1600000
#define BSTR 136   // padded row stride (bf16 elems): 272B -> conflict-free ldmatrix

// ---- scratch (__device__ globals per allocation rules) ----
__device__ __half g_mh[(size_t)MAXN * D];              // m = h @ W_nb^T (fp16)
__device__ __align__(16) __nv_bfloat16 g_wb[2 * 256 * BSTR];  // B' images
__device__ float g_bias[D];                            // b_self + b_nb
__device__ int   g_cnt[MAXN];
__device__ int   g_rowstart[MAXN];
__device__ int   g_cursor[MAXN];
__device__ int   g_scol[MAXE];
__device__ float g_sval[MAXE];
__device__ int   g_total;
__device__ int   g_is64;

// smem layout for the MMA GEMM
#define SME_B    0                          // [2][256][BSTR] bf16 = 139264 B
#define SME_A    (2 * 256 * BSTR * 2)       // [2][128][BSTR] bf16 = 69632 B
#define SME_BIAS (SME_A + 2 * 128 * BSTR * 2)
#define SME_TOTAL (SME_BIAS + 512)          // 209408 B

__device__ __forceinline__ uint32_t smem_u32(const void* p) {
    uint32_t a;
    asm("{ .reg .u64 t; cvta.to.shared.u64 t, %1; cvt.u32.u64 %0, t; }"
        : "=r"(a) : "l"(p));
    return a;
}

#define LDSM_X4(r0, r1, r2, r3, addr)                                          \
    asm volatile("ldmatrix.sync.aligned.m8n8.x4.shared.b16 {%0,%1,%2,%3}, [%4];" \
                 : "=r"(r0), "=r"(r1), "=r"(r2), "=r"(r3) : "r"(addr))

__device__ __forceinline__ void mma16816(float* c, const uint32_t* a,
                                         uint32_t b0, uint32_t b1) {
    asm volatile(
        "mma.sync.aligned.m16n8k16.row.col.f32.bf16.bf16.f32 "
        "{%0,%1,%2,%3}, {%4,%5,%6,%7}, {%8,%9}, {%0,%1,%2,%3};"
        : "+f"(c[0]), "+f"(c[1]), "+f"(c[2]), "+f"(c[3])
        : "r"(a[0]), "r"(a[1]), "r"(a[2]), "r"(a[3]), "r"(b0), "r"(b1));
}

// ---------------------------------------------------------------------------
// W precompute: B' = [W_self ; W_nb], split bf16 hi/lo, padded layout + bias.
// ---------------------------------------------------------------------------
__global__ void wconvert_kernel(const float* __restrict__ Wsf,
                                const float* __restrict__ Wnb,
                                const float* __restrict__ bsf,
                                const float* __restrict__ bnb) {
    int idx = blockIdx.x * blockDim.x + threadIdx.x;   // 0..32767
    if (idx < 256 * 128) {
        int n = idx >> 7;
        int k = idx & 127;
        float x = (n < 128) ? Wsf[n * D + k] : Wnb[(n - 128) * D + k];
        __nv_bfloat16 hi = __float2bfloat16_rn(x);
        __nv_bfloat16 lo = __float2bfloat16_rn(x - __bfloat162float(hi));
        g_wb[(size_t)n * BSTR + k] = hi;
        g_wb[(size_t)(256 + n) * BSTR + k] = lo;
    }
    if (blockIdx.x == 0 && threadIdx.x < D)
        g_bias[threadIdx.x] = bsf[threadIdx.x] + bnb[threadIdx.x];
}

// ---------------------------------------------------------------------------
// Tensor-core dual GEMM via mma.sync bf16 (split precision, virtual K=384).
// ---------------------------------------------------------------------------
__global__ __launch_bounds__(512, 1)
void gemm_mma_kernel(const float* __restrict__ h, float* __restrict__ out, int N) {
    extern __shared__ char smem[];
    const uint32_t sb = smem_u32(smem);
    const int tid = threadIdx.x;
    const int wid = tid >> 5;
    const int lane = tid & 31;
    const int r0 = blockIdx.x * 128;
    const int wrow = (wid >> 2) * 32;
    const int wcol = (wid & 3) * 64;

    {
        const uint4* src = (const uint4*)g_wb;
        uint4* dst = (uint4*)(smem + SME_B);
        for (int i = tid; i < 2 * 256 * BSTR * 2 / 16; i += 512) dst[i] = src[i];
    }
    if (tid < D) ((float*)(smem + SME_BIAS))[tid] = g_bias[tid];

    __nv_bfloat16* As = (__nv_bfloat16*)(smem + SME_A);
    for (int c = tid; c < 2048; c += 512) {
        int row = c >> 4, cc = c & 15;
        int r = r0 + row;
        float xs[8] = {0.f, 0.f, 0.f, 0.f, 0.f, 0.f, 0.f, 0.f};
        if (r < N) {
            float4 x0 = *(const float4*)&h[(size_t)r * D + cc * 8];
            float4 x1 = *(const float4*)&h[(size_t)r * D + cc * 8 + 4];
            xs[0] = x0.x; xs[1] = x0.y; xs[2] = x0.z; xs[3] = x0.w;
            xs[4] = x1.x; xs[5] = x1.y; xs[6] = x1.z; xs[7] = x1.w;
        }
        __nv_bfloat16 hi[8], lo[8];
#pragma unroll
        for (int j = 0; j < 8; j++) {
            hi[j] = __float2bfloat16_rn(xs[j]);
            lo[j] = __float2bfloat16_rn(xs[j] - __bfloat162float(hi[j]));
        }
        *(uint4*)&As[(size_t)row * BSTR + cc * 8] = *(uint4*)hi;
        *(uint4*)&As[(size_t)(128 + row) * BSTR + cc * 8] = *(uint4*)lo;
    }
    __syncthreads();

    float acc[2][8][4];
#pragma unroll
    for (int mi = 0; mi < 2; mi++)
#pragma unroll
        for (int ni = 0; ni < 8; ni++)
#pragma unroll
            for (int j = 0; j < 4; j++) acc[mi][ni][j] = 0.f;

    const int lrow = ((lane >> 3) & 1) * 8 + (lane & 7);
    const int lcol = (lane >> 4) * 8;

#pragma unroll
    for (int kb = 0; kb < 24; kb++) {
        const int asel = ((kb >> 3) == 1) ? 1 : 0;
        const int bsel = ((kb >> 3) == 2) ? 1 : 0;
        const int k0 = (kb & 7) * 16;

        uint32_t a[2][4];
#pragma unroll
        for (int mi = 0; mi < 2; mi++) {
            int row = asel * 128 + wrow + mi * 16 + lrow;
            uint32_t ad = sb + SME_A + (uint32_t)(row * BSTR + k0 + lcol) * 2;
            LDSM_X4(a[mi][0], a[mi][1], a[mi][2], a[mi][3], ad);
        }
        uint32_t b[4][4];
#pragma unroll
        for (int np = 0; np < 4; np++) {
            int nrow = bsel * 256 + wcol + np * 16 + lrow;
            uint32_t bd = sb + SME_B + (uint32_t)(nrow * BSTR + k0 + lcol) * 2;
            LDSM_X4(b[np][0], b[np][1], b[np][2], b[np][3], bd);
        }
#pragma unroll
        for (int mi = 0; mi < 2; mi++)
#pragma unroll
            for (int np = 0; np < 4; np++) {
                mma16816(acc[mi][np * 2 + 0], a[mi], b[np][0], b[np][2]);
                mma16816(acc[mi][np * 2 + 1], a[mi], b[np][1], b[np][3]);
            }
    }

    const float* sbias = (const float*)(smem + SME_BIAS);
    const int rbase = r0 + wrow + (lane >> 2);
    const int cbase = wcol + 2 * (lane & 3);

    if (wcol < 128) {
#pragma unroll
        for (int mi = 0; mi < 2; mi++)
#pragma unroll
            for (int i = 0; i < 2; i++) {
                int r = rbase + mi * 16 + 8 * i;
                if (r < N) {
#pragma unroll
                    for (int ni = 0; ni < 8; ni++) {
                        int c = cbase + ni * 8;
                        float2 v = make_float2(acc[mi][ni][2 * i] + sbias[c],
                                               acc[mi][ni][2 * i + 1] + sbias[c + 1]);
                        *(float2*)&out[(size_t)r * D + c] = v;
                    }
                }
            }
    } else {
        const int cm = cbase - 128;
#pragma unroll
        for (int mi = 0; mi < 2; mi++)
#pragma unroll
            for (int i = 0; i < 2; i++) {
                int r = rbase + mi * 16 + 8 * i;
                if (r < N) {
#pragma unroll
                    for (int ni = 0; ni < 8; ni++) {
                        int c = cm + ni * 8;
                        __half2 v = __floats2half2_rn(acc[mi][ni][2 * i],
                                                      acc[mi][ni][2 * i + 1]);
                        *(__half2*)&g_mh[(size_t)r * D + c] = v;
                    }
                }
            }
    }
}

// ---------------------------------------------------------------------------
// CSR build
// ---------------------------------------------------------------------------
__global__ void zero_detect_kernel(const int* __restrict__ er, int N) {
    int i = blockIdx.x * blockDim.x + threadIdx.x;
    if (i < N) g_cnt[i] = 0;
    if (i == 0) {
        g_total = 0;
        int f = 1;
#pragma unroll
        for (int k = 1; k < 64; k += 2) f &= (er[k] == 0);
        g_is64 = f;
    }
}

__global__ void hist_kernel(const void* __restrict__ er, int E) {
    int base = (blockIdx.x * blockDim.x + threadIdx.x) * 4;
    const int i64 = g_is64;
    int rows[4];
#pragma unroll
    for (int j = 0; j < 4; j++) {
        int e = base + j;
        rows[j] = (e < E) ? (i64 ? (int)((const long long*)er)[e]
                                 : ((const int*)er)[e])
                          : -1;
    }
#pragma unroll
    for (int j = 0; j < 4; j++)
        if (rows[j] >= 0) atomicAdd(&g_cnt[rows[j]], 1);
}

__global__ void rowassign_kernel(int N) {
    int i = blockIdx.x * blockDim.x + threadIdx.x;
    int lane = threadIdx.x & 31;
    int v = (i < N) ? g_cnt[i] : 0;
    int s = v;
#pragma unroll
    for (int off = 1; off < 32; off <<= 1) {
        int t = __shfl_up_sync(0xFFFFFFFFu, s, off);
        if (lane >= off) s += t;
    }
    int total = __shfl_sync(0xFFFFFFFFu, s, 31);
    int base = 0;
    if (lane == 31 && total > 0) base = atomicAdd(&g_total, total);
    base = __shfl_sync(0xFFFFFFFFu, base, 31);
    if (i < N) { g_rowstart[i] = base + s - v; g_cursor[i] = 0; }
}

__global__ void bucket_kernel(const float* __restrict__ ev,
                              const void* __restrict__ er,
                              const void* __restrict__ ec,
                              int E) {
    int base = (blockIdx.x * blockDim.x + threadIdx.x) * 2;
    const int i64 = g_is64;
#pragma unroll
    for (int j = 0; j < 2; j++) {
        int e = base + j;
        if (e >= E) break;
        int row, col;
        if (i64) {
            row = (int)((const long long*)er)[e];
            col = (int)((const long long*)ec)[e];
        } else {
            row = ((const int*)er)[e];
            col = ((const int*)ec)[e];
        }
        int pos = g_rowstart[row] + atomicAdd(&g_cursor[row], 1);
        g_scol[pos] = col;
        g_sval[pos] = ev[e];
    }
}

// ---------------------------------------------------------------------------
// Aggregation over fp16 m
// ---------------------------------------------------------------------------
__global__ __launch_bounds__(256)
void aggregate_kernel(float* __restrict__ out, int N) {
    const int warp = threadIdx.x >> 5;
    const int lane = threadIdx.x & 31;
    const int r = blockIdx.x * 8 + warp;
    if (r >= N) return;

    const int start = g_rowstart[r];
    const int cnt = g_cnt[r];
    if (cnt == 0) return;

    const uint2* __restrict__ m2 = (const uint2*)g_mh;
    float4 acc = make_float4(0.f, 0.f, 0.f, 0.f);

    int i = 0;
    for (; i + 4 <= cnt; i += 4) {
        int c0 = g_scol[start + i];
        int c1 = g_scol[start + i + 1];
        int c2 = g_scol[start + i + 2];
        int c3 = g_scol[start + i + 3];
        float v0 = g_sval[start + i];
        float v1 = g_sval[start + i + 1];
        float v2 = g_sval[start + i + 2];
        float v3 = g_sval[start + i + 3];
        uint2 r0 = m2[(size_t)c0 * 32 + lane];
        uint2 r1 = m2[(size_t)c1 * 32 + lane];
        uint2 r2 = m2[(size_t)c2 * 32 + lane];
        uint2 r3 = m2[(size_t)c3 * 32 + lane];
        float2 f0a = __half22float2(*(__half2*)&r0.x);
        float2 f0b = __half22float2(*(__half2*)&r0.y);
        float2 f1a = __half22float2(*(__half2*)&r1.x);
        float2 f1b = __half22float2(*(__half2*)&r1.y);
        float2 f2a = __half22float2(*(__half2*)&r2.x);
        float2 f2b = __half22float2(*(__half2*)&r2.y);
        float2 f3a = __half22float2(*(__half2*)&r3.x);
        float2 f3b = __half22float2(*(__half2*)&r3.y);
        acc.x = fmaf(v0, f0a.x, acc.x); acc.y = fmaf(v0, f0a.y, acc.y);
        acc.z = fmaf(v0, f0b.x, acc.z); acc.w = fmaf(v0, f0b.y, acc.w);
        acc.x = fmaf(v1, f1a.x, acc.x); acc.y = fmaf(v1, f1a.y, acc.y);
        acc.z = fmaf(v1, f1b.x, acc.z); acc.w = fmaf(v1, f1b.y, acc.w);
        acc.x = fmaf(v2, f2a.x, acc.x); acc.y = fmaf(v2, f2a.y, acc.y);
        acc.z = fmaf(v2, f2b.x, acc.z); acc.w = fmaf(v2, f2b.y, acc.w);
        acc.x = fmaf(v3, f3a.x, acc.x); acc.y = fmaf(v3, f3a.y, acc.y);
        acc.z = fmaf(v3, f3b.x, acc.z); acc.w = fmaf(v3, f3b.y, acc.w);
    }
    for (; i < cnt; i++) {
        int c0 = g_scol[start + i];
        float v0 = g_sval[start + i];
        uint2 r0 = m2[(size_t)c0 * 32 + lane];
        float2 f0a = __half22float2(*(__half2*)&r0.x);
        float2 f0b = __half22float2(*(__half2*)&r0.y);
        acc.x = fmaf(v0, f0a.x, acc.x); acc.y = fmaf(v0, f0a.y, acc.y);
        acc.z = fmaf(v0, f0b.x, acc.z); acc.w = fmaf(v0, f0b.y, acc.w);
    }

    float4* op = (float4*)out + (size_t)r * 32 + lane;
    float4 o = *op;
    o.x += acc.x; o.y += acc.y; o.z += acc.z; o.w += acc.w;
    *op = o;
}

// ---------------------------------------------------------------------------
extern "C" void kernel_launch(void* const* d_in, const int* in_sizes, int n_in,
                              void* d_out, int out_size) {
    const float* h   = (const float*)d_in[0];
    const float* ev  = (const float*)d_in[1];
    const float* Wsf = (const float*)d_in[2];
    const float* bsf = (const float*)d_in[3];
    const float* Wnb = (const float*)d_in[4];
    const float* bnb = (const float*)d_in[5];
    const void*  er  = d_in[6];
    const void*  ec  = d_in[7];
    float* out = (float*)d_out;

    const int N = in_sizes[0] / D;
    const int E = in_sizes[1];
    const int nbN = (N + 255) / 256;

    // one-time host-side objects (created on the non-captured correctness call)
    static cudaStream_t s_side = nullptr;
    static cudaEvent_t ev_fork = nullptr, ev_join = nullptr;
    if (s_side == nullptr) {
        cudaStreamCreateWithFlags(&s_side, cudaStreamNonBlocking);
        cudaEventCreateWithFlags(&ev_fork, cudaEventDisableTiming);
        cudaEventCreateWithFlags(&ev_join, cudaEventDisableTiming);
        cudaFuncSetAttribute(gemm_mma_kernel,
                             cudaFuncAttributeMaxDynamicSharedMemorySize, SME_TOTAL);
    }

    // fork: CSR build on side stream, GEMM chain on main stream
    cudaEventRecord(ev_fork, 0);
    cudaStreamWaitEvent(s_side, ev_fork, 0);

    zero_detect_kernel<<<nbN, 256, 0, s_side>>>((const int*)er, N);
    hist_kernel<<<(E + 1023) / 1024, 256, 0, s_side>>>(er, E);
    rowassign_kernel<<<nbN, 256, 0, s_side>>>(N);
    bucket_kernel<<<(E + 511) / 512, 256, 0, s_side>>>(ev, er, ec, E);
    cudaEventRecord(ev_join, s_side);

    wconvert_kernel<<<128, 256>>>(Wsf, Wnb, bsf, bnb);
    gemm_mma_kernel<<<(N + 127) / 128, 512, SME_TOTAL>>>(h, out, N);

    // join: aggregate needs both branches
    cudaStreamWaitEvent(0, ev_join, 0);
    aggregate_kernel<<<(N + 7) / 8, 256>>>(out, N);
}

// round 10
// speedup vs baseline: 1.5498x; 1.0607x over previous
#include <cuda_runtime.h>
#include <cuda_fp16.h>
#include <cuda_bf16.h>
#include <cstdint>

#define D 128
#define MAXN 100000
#define MAXE 1600000
#define BSTR 136   // padded row stride (bf16 elems): 272B -> conflict-free ldmatrix

// ---- scratch (__device__ globals per allocation rules) ----
__device__ __half g_mh[(size_t)MAXN * D];              // m = h @ W_nb^T (fp16)
__device__ __align__(16) __nv_bfloat16 g_wb[2 * 256 * BSTR];  // B' images
__device__ float g_bias[D];                            // b_self + b_nb
__device__ int   g_cnt[MAXN];
__device__ int   g_rowstart[MAXN];
__device__ int   g_cursor[MAXN];
__device__ int   g_scol[MAXE];
__device__ float g_sval[MAXE];
__device__ int   g_total;
__device__ int   g_is64;

// smem layout for the MMA GEMM
#define SME_B    0                          // [2][256][BSTR] bf16 = 139264 B
#define SME_A    (2 * 256 * BSTR * 2)       // [2][128][BSTR] bf16 = 69632 B
#define SME_BIAS (SME_A + 2 * 128 * BSTR * 2)
#define SME_TOTAL (SME_BIAS + 512)          // 209408 B

__device__ __forceinline__ uint32_t smem_u32(const void* p) {
    uint32_t a;
    asm("{ .reg .u64 t; cvta.to.shared.u64 t, %1; cvt.u32.u64 %0, t; }"
        : "=r"(a) : "l"(p));
    return a;
}

#define LDSM_X4(r0, r1, r2, r3, addr)                                          \
    asm volatile("ldmatrix.sync.aligned.m8n8.x4.shared.b16 {%0,%1,%2,%3}, [%4];" \
                 : "=r"(r0), "=r"(r1), "=r"(r2), "=r"(r3) : "r"(addr))

__device__ __forceinline__ void mma16816(float* c, const uint32_t* a,
                                         uint32_t b0, uint32_t b1) {
    asm volatile(
        "mma.sync.aligned.m16n8k16.row.col.f32.bf16.bf16.f32 "
        "{%0,%1,%2,%3}, {%4,%5,%6,%7}, {%8,%9}, {%0,%1,%2,%3};"
        : "+f"(c[0]), "+f"(c[1]), "+f"(c[2]), "+f"(c[3])
        : "r"(a[0]), "r"(a[1]), "r"(a[2]), "r"(a[3]), "r"(b0), "r"(b1));
}

// ---------------------------------------------------------------------------
// W precompute: B' = [W_self ; W_nb], split bf16 hi/lo, padded layout + bias.
// ---------------------------------------------------------------------------
__global__ void wconvert_kernel(const float* __restrict__ Wsf,
                                const float* __restrict__ Wnb,
                                const float* __restrict__ bsf,
                                const float* __restrict__ bnb) {
    int idx = blockIdx.x * blockDim.x + threadIdx.x;   // 0..32767
    if (idx < 256 * 128) {
        int n = idx >> 7;
        int k = idx & 127;
        float x = (n < 128) ? Wsf[n * D + k] : Wnb[(n - 128) * D + k];
        __nv_bfloat16 hi = __float2bfloat16_rn(x);
        __nv_bfloat16 lo = __float2bfloat16_rn(x - __bfloat162float(hi));
        g_wb[(size_t)n * BSTR + k] = hi;
        g_wb[(size_t)(256 + n) * BSTR + k] = lo;
    }
    if (blockIdx.x == 0 && threadIdx.x < D)
        g_bias[threadIdx.x] = bsf[threadIdx.x] + bnb[threadIdx.x];
}

// ---------------------------------------------------------------------------
// Persistent tensor-core dual GEMM (mma.sync bf16, split precision, K=384).
// B' loaded to smem ONCE per CTA; CTA loops over 128-row tiles.
// ---------------------------------------------------------------------------
__global__ __launch_bounds__(512, 1)
void gemm_mma_kernel(const float* __restrict__ h, float* __restrict__ out,
                     int N, int ntiles) {
    extern __shared__ char smem[];
    const uint32_t sb = smem_u32(smem);
    const int tid = threadIdx.x;
    const int wid = tid >> 5;
    const int lane = tid & 31;
    const int wrow = (wid >> 2) * 32;
    const int wcol = (wid & 3) * 64;

    // ---- one-time: B' images + bias
    {
        const uint4* src = (const uint4*)g_wb;
        uint4* dst = (uint4*)(smem + SME_B);
        for (int i = tid; i < 2 * 256 * BSTR * 2 / 16; i += 512) dst[i] = src[i];
    }
    if (tid < D) ((float*)(smem + SME_BIAS))[tid] = g_bias[tid];

    __nv_bfloat16* As = (__nv_bfloat16*)(smem + SME_A);
    const float* sbias = (const float*)(smem + SME_BIAS);
    const int lrow = ((lane >> 3) & 1) * 8 + (lane & 7);
    const int lcol = (lane >> 4) * 8;

    for (int t = blockIdx.x; t < ntiles; t += gridDim.x) {
        const int r0 = t * 128;

        __syncthreads();   // prev tile's ldmatrix reads done (and B' copy, 1st iter)

        // ---- load h tile, split bf16 hi/lo into A' smem
        for (int c = tid; c < 2048; c += 512) {
            int row = c >> 4, cc = c & 15;
            int r = r0 + row;
            float xs[8] = {0.f, 0.f, 0.f, 0.f, 0.f, 0.f, 0.f, 0.f};
            if (r < N) {
                float4 x0 = *(const float4*)&h[(size_t)r * D + cc * 8];
                float4 x1 = *(const float4*)&h[(size_t)r * D + cc * 8 + 4];
                xs[0] = x0.x; xs[1] = x0.y; xs[2] = x0.z; xs[3] = x0.w;
                xs[4] = x1.x; xs[5] = x1.y; xs[6] = x1.z; xs[7] = x1.w;
            }
            __nv_bfloat16 hi[8], lo[8];
#pragma unroll
            for (int j = 0; j < 8; j++) {
                hi[j] = __float2bfloat16_rn(xs[j]);
                lo[j] = __float2bfloat16_rn(xs[j] - __bfloat162float(hi[j]));
            }
            *(uint4*)&As[(size_t)row * BSTR + cc * 8] = *(uint4*)hi;
            *(uint4*)&As[(size_t)(128 + row) * BSTR + cc * 8] = *(uint4*)lo;
        }
        __syncthreads();

        // ---- compute
        float acc[2][8][4];
#pragma unroll
        for (int mi = 0; mi < 2; mi++)
#pragma unroll
            for (int ni = 0; ni < 8; ni++)
#pragma unroll
                for (int j = 0; j < 4; j++) acc[mi][ni][j] = 0.f;

#pragma unroll
        for (int kb = 0; kb < 24; kb++) {
            const int asel = ((kb >> 3) == 1) ? 1 : 0;
            const int bsel = ((kb >> 3) == 2) ? 1 : 0;
            const int k0 = (kb & 7) * 16;

            uint32_t a[2][4];
#pragma unroll
            for (int mi = 0; mi < 2; mi++) {
                int row = asel * 128 + wrow + mi * 16 + lrow;
                uint32_t ad = sb + SME_A + (uint32_t)(row * BSTR + k0 + lcol) * 2;
                LDSM_X4(a[mi][0], a[mi][1], a[mi][2], a[mi][3], ad);
            }
            uint32_t b[4][4];
#pragma unroll
            for (int np = 0; np < 4; np++) {
                int nrow = bsel * 256 + wcol + np * 16 + lrow;
                uint32_t bd = sb + SME_B + (uint32_t)(nrow * BSTR + k0 + lcol) * 2;
                LDSM_X4(b[np][0], b[np][1], b[np][2], b[np][3], bd);
            }
#pragma unroll
            for (int mi = 0; mi < 2; mi++)
#pragma unroll
                for (int np = 0; np < 4; np++) {
                    mma16816(acc[mi][np * 2 + 0], a[mi], b[np][0], b[np][2]);
                    mma16816(acc[mi][np * 2 + 1], a[mi], b[np][1], b[np][3]);
                }
        }

        // ---- epilogue
        const int rbase = r0 + wrow + (lane >> 2);
        const int cbase = wcol + 2 * (lane & 3);

        if (wcol < 128) {
#pragma unroll
            for (int mi = 0; mi < 2; mi++)
#pragma unroll
                for (int i = 0; i < 2; i++) {
                    int r = rbase + mi * 16 + 8 * i;
                    if (r < N) {
#pragma unroll
                        for (int ni = 0; ni < 8; ni++) {
                            int c = cbase + ni * 8;
                            float2 v = make_float2(acc[mi][ni][2 * i] + sbias[c],
                                                   acc[mi][ni][2 * i + 1] + sbias[c + 1]);
                            *(float2*)&out[(size_t)r * D + c] = v;
                        }
                    }
                }
        } else {
            const int cm = cbase - 128;
#pragma unroll
            for (int mi = 0; mi < 2; mi++)
#pragma unroll
                for (int i = 0; i < 2; i++) {
                    int r = rbase + mi * 16 + 8 * i;
                    if (r < N) {
#pragma unroll
                        for (int ni = 0; ni < 8; ni++) {
                            int c = cm + ni * 8;
                            __half2 v = __floats2half2_rn(acc[mi][ni][2 * i],
                                                          acc[mi][ni][2 * i + 1]);
                            *(__half2*)&g_mh[(size_t)r * D + c] = v;
                        }
                    }
                }
        }
    }
}

// ---------------------------------------------------------------------------
// CSR build
// ---------------------------------------------------------------------------
__global__ void zero_detect_kernel(const int* __restrict__ er, int N) {
    int i = blockIdx.x * blockDim.x + threadIdx.x;
    if (i < N) g_cnt[i] = 0;
    if (i == 0) {
        g_total = 0;
        int f = 1;
#pragma unroll
        for (int k = 1; k < 64; k += 2) f &= (er[k] == 0);
        g_is64 = f;
    }
}

__global__ void hist_kernel(const void* __restrict__ er, int E) {
    int base = (blockIdx.x * blockDim.x + threadIdx.x) * 4;
    const int i64 = g_is64;
    int rows[4];
#pragma unroll
    for (int j = 0; j < 4; j++) {
        int e = base + j;
        rows[j] = (e < E) ? (i64 ? (int)((const long long*)er)[e]
                                 : ((const int*)er)[e])
                          : -1;
    }
#pragma unroll
    for (int j = 0; j < 4; j++)
        if (rows[j] >= 0) atomicAdd(&g_cnt[rows[j]], 1);
}

__global__ void rowassign_kernel(int N) {
    int i = blockIdx.x * blockDim.x + threadIdx.x;
    int lane = threadIdx.x & 31;
    int v = (i < N) ? g_cnt[i] : 0;
    int s = v;
#pragma unroll
    for (int off = 1; off < 32; off <<= 1) {
        int t = __shfl_up_sync(0xFFFFFFFFu, s, off);
        if (lane >= off) s += t;
    }
    int total = __shfl_sync(0xFFFFFFFFu, s, 31);
    int base = 0;
    if (lane == 31 && total > 0) base = atomicAdd(&g_total, total);
    base = __shfl_sync(0xFFFFFFFFu, base, 31);
    if (i < N) { g_rowstart[i] = base + s - v; g_cursor[i] = 0; }
}

__global__ void bucket_kernel(const float* __restrict__ ev,
                              const void* __restrict__ er,
                              const void* __restrict__ ec,
                              int E) {
    int base = (blockIdx.x * blockDim.x + threadIdx.x) * 2;
    const int i64 = g_is64;
#pragma unroll
    for (int j = 0; j < 2; j++) {
        int e = base + j;
        if (e >= E) break;
        int row, col;
        if (i64) {
            row = (int)((const long long*)er)[e];
            col = (int)((const long long*)ec)[e];
        } else {
            row = ((const int*)er)[e];
            col = ((const int*)ec)[e];
        }
        int pos = g_rowstart[row] + atomicAdd(&g_cursor[row], 1);
        g_scol[pos] = col;
        g_sval[pos] = ev[e];
    }
}

// ---------------------------------------------------------------------------
// Aggregation over fp16 m
// ---------------------------------------------------------------------------
__global__ __launch_bounds__(256)
void aggregate_kernel(float* __restrict__ out, int N) {
    const int warp = threadIdx.x >> 5;
    const int lane = threadIdx.x & 31;
    const int r = blockIdx.x * 8 + warp;
    if (r >= N) return;

    const int start = g_rowstart[r];
    const int cnt = g_cnt[r];
    if (cnt == 0) return;

    const uint2* __restrict__ m2 = (const uint2*)g_mh;
    float4 acc = make_float4(0.f, 0.f, 0.f, 0.f);

    int i = 0;
    for (; i + 4 <= cnt; i += 4) {
        int c0 = g_scol[start + i];
        int c1 = g_scol[start + i + 1];
        int c2 = g_scol[start + i + 2];
        int c3 = g_scol[start + i + 3];
        float v0 = g_sval[start + i];
        float v1 = g_sval[start + i + 1];
        float v2 = g_sval[start + i + 2];
        float v3 = g_sval[start + i + 3];
        uint2 r0 = m2[(size_t)c0 * 32 + lane];
        uint2 r1 = m2[(size_t)c1 * 32 + lane];
        uint2 r2 = m2[(size_t)c2 * 32 + lane];
        uint2 r3 = m2[(size_t)c3 * 32 + lane];
        float2 f0a = __half22float2(*(__half2*)&r0.x);
        float2 f0b = __half22float2(*(__half2*)&r0.y);
        float2 f1a = __half22float2(*(__half2*)&r1.x);
        float2 f1b = __half22float2(*(__half2*)&r1.y);
        float2 f2a = __half22float2(*(__half2*)&r2.x);
        float2 f2b = __half22float2(*(__half2*)&r2.y);
        float2 f3a = __half22float2(*(__half2*)&r3.x);
        float2 f3b = __half22float2(*(__half2*)&r3.y);
        acc.x = fmaf(v0, f0a.x, acc.x); acc.y = fmaf(v0, f0a.y, acc.y);
        acc.z = fmaf(v0, f0b.x, acc.z); acc.w = fmaf(v0, f0b.y, acc.w);
        acc.x = fmaf(v1, f1a.x, acc.x); acc.y = fmaf(v1, f1a.y, acc.y);
        acc.z = fmaf(v1, f1b.x, acc.z); acc.w = fmaf(v1, f1b.y, acc.w);
        acc.x = fmaf(v2, f2a.x, acc.x); acc.y = fmaf(v2, f2a.y, acc.y);
        acc.z = fmaf(v2, f2b.x, acc.z); acc.w = fmaf(v2, f2b.y, acc.w);
        acc.x = fmaf(v3, f3a.x, acc.x); acc.y = fmaf(v3, f3a.y, acc.y);
        acc.z = fmaf(v3, f3b.x, acc.z); acc.w = fmaf(v3, f3b.y, acc.w);
    }
    for (; i < cnt; i++) {
        int c0 = g_scol[start + i];
        float v0 = g_sval[start + i];
        uint2 r0 = m2[(size_t)c0 * 32 + lane];
        float2 f0a = __half22float2(*(__half2*)&r0.x);
        float2 f0b = __half22float2(*(__half2*)&r0.y);
        acc.x = fmaf(v0, f0a.x, acc.x); acc.y = fmaf(v0, f0a.y, acc.y);
        acc.z = fmaf(v0, f0b.x, acc.z); acc.w = fmaf(v0, f0b.y, acc.w);
    }

    float4* op = (float4*)out + (size_t)r * 32 + lane;
    float4 o = *op;
    o.x += acc.x; o.y += acc.y; o.z += acc.z; o.w += acc.w;
    *op = o;
}

// ---------------------------------------------------------------------------
extern "C" void kernel_launch(void* const* d_in, const int* in_sizes, int n_in,
                              void* d_out, int out_size) {
    const float* h   = (const float*)d_in[0];
    const float* ev  = (const float*)d_in[1];
    const float* Wsf = (const float*)d_in[2];
    const float* bsf = (const float*)d_in[3];
    const float* Wnb = (const float*)d_in[4];
    const float* bnb = (const float*)d_in[5];
    const void*  er  = d_in[6];
    const void*  ec  = d_in[7];
    float* out = (float*)d_out;

    const int N = in_sizes[0] / D;
    const int E = in_sizes[1];
    const int nbN = (N + 255) / 256;
    const int ntiles = (N + 127) / 128;

    // one-time host-side objects (created on the non-captured correctness call)
    static cudaStream_t s_side = nullptr;
    static cudaEvent_t ev_fork = nullptr, ev_join = nullptr;
    static int n_sm = 148;
    if (s_side == nullptr) {
        cudaStreamCreateWithFlags(&s_side, cudaStreamNonBlocking);
        cudaEventCreateWithFlags(&ev_fork, cudaEventDisableTiming);
        cudaEventCreateWithFlags(&ev_join, cudaEventDisableTiming);
        cudaFuncSetAttribute(gemm_mma_kernel,
                             cudaFuncAttributeMaxDynamicSharedMemorySize, SME_TOTAL);
        cudaDeviceGetAttribute(&n_sm, cudaDevAttrMultiProcessorCount, 0);
    }

    // fork: CSR build on side stream, GEMM chain on main stream
    cudaEventRecord(ev_fork, 0);
    cudaStreamWaitEvent(s_side, ev_fork, 0);

    zero_detect_kernel<<<nbN, 256, 0, s_side>>>((const int*)er, N);
    hist_kernel<<<(E + 1023) / 1024, 256, 0, s_side>>>(er, E);
    rowassign_kernel<<<nbN, 256, 0, s_side>>>(N);
    bucket_kernel<<<(E + 511) / 512, 256, 0, s_side>>>(ev, er, ec, E);
    cudaEventRecord(ev_join, s_side);

    wconvert_kernel<<<128, 256>>>(Wsf, Wnb, bsf, bnb);
    const int ngrid = (ntiles < n_sm) ? ntiles : n_sm;
    gemm_mma_kernel<<<ngrid, 512, SME_TOTAL>>>(h, out, N, ntiles);

    // join: aggregate needs both branches
    cudaStreamWaitEvent(0, ev_join, 0);
    aggregate_kernel<<<(N + 7) / 8, 256>>>(out, N);
}